// round 4
// baseline (speedup 1.0000x reference)
#include <cuda_runtime.h>
#include <cuda_bf16.h>

// Problem constants: N boxes (dynamic), C=256, G=7, dims {38,19,10,5,3,1}
#define ROI_C   256
#define ROI_G   7
#define ROI_GG  49
#define ROI_ELEMS_PER_BOX (ROI_C * ROI_GG)   // 12544
#define G4_TOTAL 496640                      // sum over levels of 256*D*D

// g4buf layout: [level][cell][channel] float4 -> a warp reading 32 consecutive
// channels of one cell fetches 512B contiguous (L1 wavefront floor).
static __device__ float4 g4buf[G4_TOTAL];    // 7.94 MB, L2-resident

__constant__ int c_bnd[7] = {0, 369664, 462080, 487680, 494080, 496384, 496640};
__constant__ int c_Dc[6]  = {38, 19, 10, 5, 3, 1};

// ---------------------------------------------------------------------------
// Prep: pack 4 bilinear corners of cell (x,y), channel c, into
// g4buf[base + (x*D+y)*256 + c] = (v[x,y], v[x,y+1], v[x+1,y], v[x+1,y+1]).
// Thread index is READ-friendly (cell fastest -> coalesced fmap reads);
// the 16B writes scatter (stride 4KB) but total only ~0.5M wavefronts (~2us).
// ---------------------------------------------------------------------------
template <int D>
__device__ __forceinline__ void pack_level(const float* __restrict__ f,
                                           int local, int base) {
    const int DD = D * D;
    const int c    = local / DD;        // compile-time D -> mul-by-reciprocal
    const int cell = local - c * DD;
    const int x = cell / D;
    const int y = cell - x * D;
    const float* fc = f + c * DD;
    const int xp = (x + 1 < D) ? x + 1 : D - 1;
    const int yp = (y + 1 < D) ? y + 1 : D - 1;
    g4buf[base + cell * 256 + c] = make_float4(fc[x * D + y],  fc[x * D + yp],
                                               fc[xp * D + y], fc[xp * D + yp]);
}

__global__ void prep_kernel(const float* __restrict__ f0, const float* __restrict__ f1,
                            const float* __restrict__ f2, const float* __restrict__ f3,
                            const float* __restrict__ f4, const float* __restrict__ f5) {
    int idx = blockIdx.x * blockDim.x + threadIdx.x;
    if (idx >= G4_TOTAL) return;

    int l = 0;
    #pragma unroll
    for (int j = 1; j < 6; ++j) l += (idx >= c_bnd[j]) ? 1 : 0;
    const int local = idx - c_bnd[l];
    const int base  = c_bnd[l];

    switch (l) {
        case 0: pack_level<38>(f0, local, base); break;
        case 1: pack_level<19>(f1, local, base); break;
        case 2: pack_level<10>(f2, local, base); break;
        case 3: pack_level<5>(f3, local, base); break;
        case 4: pack_level<3>(f4, local, base); break;
        default: pack_level<1>(f5, local, base); break;
    }
}

// ---------------------------------------------------------------------------
// Main: one block (512 thr) per box.
//  phase 0: threads 0..48 compute per-grid-cell g4 offset + 4 weights -> smem
//  phase 1: warp lanes = consecutive channels of ONE cell -> 512B coalesced
//           LDG.128; result staged to smem at [c%128]*49+cell (odd stride =
//           conflict-free). Two 128-channel halves keep static smem < 26KB.
//  phase 2: coalesced float4 copy smem -> out.
// ---------------------------------------------------------------------------
__global__ __launch_bounds__(512)
void roi_kernel(const float* __restrict__ boxes, float* __restrict__ out) {
    __shared__ float  s_out[128 * ROI_GG];   // 25088 B
    __shared__ float4 s_w[ROI_GG];
    __shared__ int    s_off[ROI_GG];

    const int n = blockIdx.x;
    const int t = threadIdx.x;

    const float bx1 = __ldg(boxes + 4 * n + 0);
    const float by1 = __ldg(boxes + 4 * n + 1);
    const float bx2 = __ldg(boxes + 4 * n + 2);
    const float by2 = __ldg(boxes + 4 * n + 3);

    const float avg = sqrtf((bx2 - bx1) * (by2 - by1));
    int lvl = (int)floorf(5.0f + log2f(avg));
    lvl = max(0, min(5, lvl));
    const int D    = c_Dc[lvl];
    const int base = c_bnd[lvl];

    if (t < ROI_GG) {
        const int gi = t / ROI_G;
        const int gj = t - gi * ROI_G;
        const float Dm1 = (float)(D - 1);
        const float fx = fminf(fmaxf(bx1 + ((float)gi * (bx2 - bx1)) / 6.0f, 0.0f), 1.0f);
        const float fy = fminf(fmaxf(by1 + ((float)gj * (by2 - by1)) / 6.0f, 0.0f), 1.0f);
        const float ux = fx * Dm1;
        const float uy = fy * Dm1;
        const float x0f = floorf(ux);
        const float y0f = floorf(uy);
        const float px0 = 1.0f - (ux - x0f);
        const float px1 = 1.0f - px0;
        const float py0 = 1.0f - (uy - y0f);
        const float py1 = 1.0f - py0;
        const int ix0 = (int)x0f;
        const int iy0 = (int)y0f;
        s_off[t] = base + (ix0 * D + iy0) * 256;
        s_w[t]   = make_float4(px0 * py0, px0 * py1, px1 * py0, px1 * py1);
    }
    __syncthreads();

    const int c_lane   = t & 127;        // channel within half
    const int cell_grp = t >> 7;         // 0..3 : 4 cells processed per iter
    float* outn = out + (size_t)n * ROI_ELEMS_PER_BOX;

    #pragma unroll
    for (int h = 0; h < 2; ++h) {
        const int c = h * 128 + c_lane;
        #pragma unroll
        for (int it = 0; it < 13; ++it) {
            const int cell = it * 4 + cell_grp;
            if (cell < ROI_GG) {
                const float4 w = s_w[cell];
                const float4 p = __ldg(&g4buf[s_off[cell] + c]);
                s_out[c_lane * ROI_GG + cell] =
                    w.x * p.x + w.y * p.y + w.z * p.z + w.w * p.w;
            }
        }
        __syncthreads();
        const float4* s4 = (const float4*)s_out;
        float4*       o4 = (float4*)(outn + h * (128 * ROI_GG));
        #pragma unroll
        for (int j = t; j < (128 * ROI_GG) / 4; j += 512)  // 1568 float4
            o4[j] = s4[j];
        __syncthreads();
    }
}

// ---------------------------------------------------------------------------
extern "C" void kernel_launch(void* const* d_in, const int* in_sizes, int n_in,
                              void* d_out, int out_size) {
    const float* boxes = (const float*)d_in[0];
    const float* f0 = (const float*)d_in[1];
    const float* f1 = (const float*)d_in[2];
    const float* f2 = (const float*)d_in[3];
    const float* f3 = (const float*)d_in[4];
    const float* f4 = (const float*)d_in[5];
    const float* f5 = (const float*)d_in[6];

    const int N = in_sizes[0] / 4;

    prep_kernel<<<(G4_TOTAL + 255) / 256, 256>>>(f0, f1, f2, f3, f4, f5);
    roi_kernel<<<N, 512>>>(boxes, (float*)d_out);
}

// round 7
// speedup vs baseline: 1.2713x; 1.2713x over previous
#include <cuda_runtime.h>
#include <cuda_bf16.h>

// N boxes (dynamic), C=256, G=7, fmap dims {38,19,10,5,3,1}
#define ROI_G    7
#define ROI_GG   49
#define ROI_EPB  12544          // 256*49
#define TF_TOTAL 496640         // sum over levels of D*D*256
#define MAXPB    5              // provable bound on short-axis patch size
#define MAXNR    35             // 7*MAXPB
#define RSTRIDE  257            // odd -> distinct rows hit distinct banks

// Channel-last transposed fmaps: tf[level][x*D+y][c]  (1.99 MB, L2-resident)
static __device__ float tfmap[TF_TOTAL];

__constant__ int c_bnd[7] = {0, 369664, 462080, 487680, 494080, 496384, 496640};
__constant__ int c_Dc[6]  = {38, 19, 10, 5, 3, 1};

// ---------------------------------------------------------------------------
// Prep: transpose fmap[c][x][y] -> tfmap[(x*D+y)*256 + c]. Writes coalesced;
// reads scatter but fmaps total 2MB (L2-hot, heavy sector reuse across blocks).
// ---------------------------------------------------------------------------
__global__ void prep_kernel(const float* __restrict__ f0, const float* __restrict__ f1,
                            const float* __restrict__ f2, const float* __restrict__ f3,
                            const float* __restrict__ f4, const float* __restrict__ f5) {
    int idx = blockIdx.x * blockDim.x + threadIdx.x;
    if (idx >= TF_TOTAL) return;
    int l = 0;
    #pragma unroll
    for (int j = 1; j < 6; ++j) l += (idx >= c_bnd[j]) ? 1 : 0;
    const float* f; int D;
    switch (l) {
        case 0: f = f0; D = 38; break;
        case 1: f = f1; D = 19; break;
        case 2: f = f2; D = 10; break;
        case 3: f = f3; D = 5;  break;
        case 4: f = f4; D = 3;  break;
        default:f = f5; D = 1;  break;
    }
    const int local = idx - c_bnd[l];
    const int xy = local >> 8;
    const int c  = local & 255;
    tfmap[idx] = f[c * D * D + xy];
}

// ---------------------------------------------------------------------------
// Main: one block (512 thr) per box. Separable bilinear:
//  pass 1: lerp along the LONG box axis straight from tfmap (coalesced LDG.128)
//          into s_r[7 * PB][256]  (PB = short-axis patch size <= 5)
//  pass 2: lerp along the short axis from s_r; thread owns one grid cell
//          (slot = t&63), channels strided by 8 -> weights/rows in registers,
//          stores coalesced STG.32.
// ---------------------------------------------------------------------------
__global__ __launch_bounds__(512)
void roi_kernel(const float* __restrict__ boxes, float* __restrict__ out) {
    __shared__ float  s_r[MAXNR * RSTRIDE];     // 35.1 KB
    __shared__ int    s_o0[MAXNR], s_o1[MAXNR];
    __shared__ float  s_a0[MAXNR], s_a1[MAXNR];
    __shared__ float4 s_tab[ROI_GG];            // (w0, w1, row0_bits, row1_bits)
    __shared__ int    s_i0[14], s_i1[14];       // [0..6]=x samples, [7..13]=y
    __shared__ float  s_p0[14], s_p1[14];
    __shared__ int    s_meta[3];                // xfirst, blo, PB

    const int n = blockIdx.x;
    const int t = threadIdx.x;

    const float bx1 = __ldg(boxes + 4 * n + 0);
    const float by1 = __ldg(boxes + 4 * n + 1);
    const float bx2 = __ldg(boxes + 4 * n + 2);
    const float by2 = __ldg(boxes + 4 * n + 3);

    const float avg = sqrtf((bx2 - bx1) * (by2 - by1));
    int lvl = (int)floorf(5.0f + log2f(avg));
    lvl = max(0, min(5, lvl));
    const int D    = c_Dc[lvl];
    const int base = c_bnd[lvl];

    // 14 sample sets: floor/ceil indices + proportion weights (ref-exact)
    if (t < 14) {
        const int axis = t / 7, g = t - axis * 7;
        const float lo = axis ? by1 : bx1;
        const float hi = axis ? by2 : bx2;
        const float fr = fminf(fmaxf(lo + ((float)g * (hi - lo)) / 6.0f, 0.0f), 1.0f);
        const float u  = fr * (float)(D - 1);
        const float u0 = floorf(u);
        s_i0[t] = (int)u0;
        s_i1[t] = (int)ceilf(u);
        const float p0 = 1.0f - (u - u0);       // ddx==1 convention of the ref
        s_p0[t] = p0;
        s_p1[t] = 1.0f - p0;
    }
    __syncthreads();

    if (t == 0) {
        const int PX = s_i1[6]  - s_i0[0] + 1;
        const int PY = s_i1[13] - s_i0[7] + 1;
        const int xf = (PX >= PY) ? 1 : 0;      // lerp the longer axis first
        s_meta[0] = xf;
        s_meta[1] = xf ? s_i0[7] : s_i0[0];     // blo: short-axis patch start
        s_meta[2] = min(xf ? PY : PX, MAXPB);   // PB (bound is provable; clamp=safety)
    }
    __syncthreads();
    const int xf  = s_meta[0];
    const int blo = s_meta[1];
    const int PB  = s_meta[2];
    const int NR  = 7 * PB;

    // Pass-1 row tables: row = ga*PB + bb (ga = long-axis sample, bb = patch col)
    if (t < NR) {
        const int ga = t / PB;
        const int bb = t - ga * PB;
        const int aoff = xf ? 0 : 7;
        const int a0 = s_i0[aoff + ga], a1 = s_i1[aoff + ga];
        const int b  = blo + bb;
        const int adr0 = xf ? (a0 * D + b) : (b * D + a0);
        const int adr1 = xf ? (a1 * D + b) : (b * D + a1);
        s_o0[t] = base + (adr0 << 8);
        s_o1[t] = base + (adr1 << 8);
        s_a0[t] = s_p0[aoff + ga];
        s_a1[t] = s_p1[aoff + ga];
    }
    // Pass-2 per-cell table
    if (t < ROI_GG) {
        const int gi = t / ROI_G, gj = t - gi * ROI_G;
        const int ga = xf ? gi : gj;
        const int gb = xf ? (7 + gj) : gi;
        const int b0 = min(max(s_i0[gb] - blo, 0), PB - 1);
        const int b1 = min(max(s_i1[gb] - blo, 0), PB - 1);
        s_tab[t] = make_float4(s_p0[gb], s_p1[gb],
                               __int_as_float((ga * PB + b0) * RSTRIDE),
                               __int_as_float((ga * PB + b1) * RSTRIDE));
    }
    __syncthreads();

    // ---- pass 1: NR rows x 256 ch, float4 over channels (<=5 iters/thread)
    const int tot1 = NR << 6;                   // NR * 64 float4 groups
    for (int j = t; j < tot1; j += 512) {
        const int row = j >> 6;
        const int c4  = (j & 63) << 2;
        const float a0 = s_a0[row], a1 = s_a1[row];
        const float4 v0 = *(const float4*)&tfmap[s_o0[row] + c4];
        const float4 v1 = *(const float4*)&tfmap[s_o1[row] + c4];
        float* rp = &s_r[row * RSTRIDE + c4];   // scalar STS keeps stride-257
        rp[0] = a0 * v0.x + a1 * v1.x;          // bank pattern conflict-free
        rp[1] = a0 * v0.y + a1 * v1.y;
        rp[2] = a0 * v0.z + a1 * v1.z;
        rp[3] = a0 * v0.w + a1 * v1.w;
    }
    __syncthreads();

    // ---- pass 2: slot = t&63 (cell, idle if >=49), cgrp = t>>6, c = cgrp+8k
    const int slot = t & 63;
    const int cgrp = t >> 6;
    float* outn = out + (size_t)n * ROI_EPB;
    if (slot < ROI_GG) {
        const float4 tab = s_tab[slot];
        const float w0 = tab.x, w1 = tab.y;
        const int r0 = __float_as_int(tab.z);
        const int r1 = __float_as_int(tab.w);
        #pragma unroll
        for (int k = 0; k < 32; ++k) {
            const int c = cgrp + (k << 3);      // covers 0..255 exactly
            outn[c * ROI_GG + slot] = w0 * s_r[r0 + c] + w1 * s_r[r1 + c];
        }
    }
}

// ---------------------------------------------------------------------------
extern "C" void kernel_launch(void* const* d_in, const int* in_sizes, int n_in,
                              void* d_out, int out_size) {
    const float* boxes = (const float*)d_in[0];
    const float* f0 = (const float*)d_in[1];
    const float* f1 = (const float*)d_in[2];
    const float* f2 = (const float*)d_in[3];
    const float* f3 = (const float*)d_in[4];
    const float* f4 = (const float*)d_in[5];
    const float* f5 = (const float*)d_in[6];

    const int N = in_sizes[0] / 4;

    prep_kernel<<<(TF_TOTAL + 255) / 256, 256>>>(f0, f1, f2, f3, f4, f5);
    roi_kernel<<<N, 512>>>(boxes, (float*)d_out);
}